// round 2
// baseline (speedup 1.0000x reference)
#include <cuda_runtime.h>
#include <stdint.h>

#define TT   4
#define NN   20000
#define EE   320000
#define FF   64
#define HH   64
#define TSN  50
#define G4H  256      // 4 gates * H
#define KA   192      // agg_x(64) | x_norm(64) | agg_h(64)
#define KSEL 10000    // top-k

// ---------------- device scratch (static, allocation-free) ----------------
__device__ __align__(16) float g_A[NN * KA];
__device__ __align__(16) float g_gates[NN * G4H];
__device__ __align__(16) float g_h[NN * HH];
__device__ __align__(16) float g_c[NN * HH];
__device__ float g_degacc[NN];
__device__ float g_dinv[NN];
__device__ float g_self[NN];
__device__ float g_gcn[EE];
__device__ int   g_src[EE];
__device__ int   g_dst[EE];
__device__ int   g_is64;
__device__ __align__(16) float g_Wc[KA * G4H];
__device__ __align__(16) float g_bc[G4H];
__device__ float g_colsum[FF];
__device__ float g_colsq[FF];
__device__ float g_mean[FF];
__device__ float g_rinv[FF];
__device__ float g_v[HH];
__device__ float g_raw[NN];
__device__ float g_sig[NN];
__device__ unsigned g_key[NN];
__device__ float g_high[HH];
__device__ __align__(16) float g_G[TSN * G4H];
__device__ float g_hl[HH];
__device__ unsigned g_hist[256];
__device__ unsigned g_prefix;
__device__ unsigned g_kk;
__device__ unsigned g_ticket;
__device__ float g_ssum, g_ssq, g_smean, g_sinv, g_ploss;

__device__ __forceinline__ float sigm(float x) { return 1.f / (1.f + expf(-x)); }

// ---------------- edge-index dtype detection + decode ----------------
__global__ void k_detect(const void* eiraw) {
    if (threadIdx.x == 0) {
        const long long* p = (const long long*)eiraw;
        int ok = 1;
        for (int i = 0; i < 8; i++) {
            long long v = p[i];
            if (v < 0 || v >= NN) ok = 0;
        }
        g_is64 = ok;
    }
}

__global__ void k_decode(const void* eiraw) {
    int e = blockIdx.x * blockDim.x + threadIdx.x;
    if (e >= EE) return;
    int s, d;
    if (g_is64) {
        const long long* p = (const long long*)eiraw;
        s = (int)p[e];
        d = (int)p[EE + e];
    } else {
        const int* p = (const int*)eiraw;
        s = p[e];
        d = p[EE + e];
    }
    s = min(max(s, 0), NN - 1);
    d = min(max(d, 0), NN - 1);
    g_src[e] = s;
    g_dst[e] = d;
}

// ---------------- init / graph-structure kernels ----------------
__global__ void k_zero_misc() {
    int i = blockIdx.x * blockDim.x + threadIdx.x;
    if (i < NN) g_degacc[i] = 0.f;
    if (i < TSN * G4H) g_G[i] = 0.f;
    if (i < HH) g_high[i] = 0.f;
    if (i < 256) g_hist[i] = 0u;
    if (i == 0) {
        g_prefix = 0u; g_kk = KSEL; g_ticket = 0u;
        g_ssum = 0.f; g_ssq = 0.f; g_ploss = 0.f;
    }
}

__global__ void k_deg() {
    int e = blockIdx.x * blockDim.x + threadIdx.x;
    if (e < EE) atomicAdd(&g_degacc[g_dst[e]], 1.f);
}

__global__ void k_init_nodes(const float* __restrict__ h0, const float* __restrict__ c0) {
    int i = blockIdx.x * blockDim.x + threadIdx.x;
    if (i < NN) {
        float d = g_degacc[i] + 1.f;
        g_dinv[i] = rsqrtf(d);
        g_self[i] = 1.f / d;
    }
    if (i < NN * HH) { g_h[i] = h0[i]; g_c[i] = c0[i]; }
}

__global__ void k_gcn() {
    int e = blockIdx.x * blockDim.x + threadIdx.x;
    if (e < EE) g_gcn[e] = g_dinv[g_src[e]] * g_dinv[g_dst[e]];
}

__global__ void k_wc(const float* __restrict__ Wrel, const float* __restrict__ brel,
                     const float* __restrict__ Wroot, const float* __restrict__ Wg,
                     const float* __restrict__ bg) {
    int idx = blockIdx.x * blockDim.x + threadIdx.x;
    if (idx < KA * G4H) {
        int k = idx / G4H, col = idx % G4H;
        int g = col >> 6, h2 = col & 63;
        float w;
        if (k < 64)       w = Wrel [g * 4096 + k * 64 + h2];
        else if (k < 128) w = Wroot[g * 4096 + (k - 64) * 64 + h2];
        else              w = Wg   [g * 4096 + (k - 128) * 64 + h2];
        g_Wc[idx] = w;
    }
    if (idx < G4H) g_bc[idx] = brel[idx] + bg[idx];
}

// ---------------- per-timestep kernels ----------------
__global__ void k_zstats() {
    int f = threadIdx.x;
    g_colsum[f] = 0.f; g_colsq[f] = 0.f;
}

__global__ void k_colstats(const float* __restrict__ xt) {
    __shared__ float ss[256], sq[256];
    int f = threadIdx.x & 63, slot = threadIdx.x >> 6;
    float s = 0.f, q = 0.f;
    for (int n = blockIdx.x * 4 + slot; n < NN; n += gridDim.x * 4) {
        float v = xt[n * 64 + f];
        s += v; q += v * v;
    }
    ss[threadIdx.x] = s; sq[threadIdx.x] = q;
    __syncthreads();
    if (slot == 0) {
        s = ss[f] + ss[f + 64] + ss[f + 128] + ss[f + 192];
        q = sq[f] + sq[f + 64] + sq[f + 128] + sq[f + 192];
        atomicAdd(&g_colsum[f], s);
        atomicAdd(&g_colsq[f], q);
    }
}

__global__ void k_statsfin() {
    int f = threadIdx.x;
    float s = g_colsum[f], q = g_colsq[f];
    float mean = s * (1.f / NN);
    float var = (q - s * s * (1.f / NN)) * (1.f / (NN - 1));
    float sd = sqrtf(fmaxf(var, 0.f));
    g_mean[f] = mean;
    g_rinv[f] = 1.f / (sd + 1e-6f);
}

__global__ void k_prep(const float* __restrict__ xt) {
    int i = blockIdx.x * blockDim.x + threadIdx.x;
    if (i >= NN * FF) return;
    int n = i >> 6, f = i & 63;
    float xn = (xt[i] - g_mean[f]) * g_rinv[f];
    float* Ar = g_A + (long)n * KA;
    Ar[f] = 0.f;                       // agg_x accumulator
    Ar[64 + f] = xn;                   // normalized x
    Ar[128 + f] = g_self[n] * g_h[i];  // GCN self-loop term (agg_h accumulator seed)
}

__global__ void k_scatter(const float* __restrict__ w) {
    int gw = (blockIdx.x * blockDim.x + threadIdx.x) >> 5;
    int lane = threadIdx.x & 31;
    if (gw >= EE) return;
    int s = 0, d = 0; float ww = 0.f, gn = 0.f;
    if (lane == 0) {
        s = g_src[gw]; d = g_dst[gw];
        ww = w[gw]; gn = g_gcn[gw];
    }
    s  = __shfl_sync(0xffffffffu, s, 0);
    d  = __shfl_sync(0xffffffffu, d, 0);
    ww = __shfl_sync(0xffffffffu, ww, 0);
    gn = __shfl_sync(0xffffffffu, gn, 0);
    const float* As = g_A + (long)s * KA + 64;
    const float* hs = g_h + (long)s * 64;
    float* Ad = g_A + (long)d * KA;
    atomicAdd(Ad + lane,          ww * As[lane]);
    atomicAdd(Ad + lane + 32,     ww * As[lane + 32]);
    atomicAdd(Ad + 128 + lane,       gn * hs[lane]);
    atomicAdd(Ad + 128 + lane + 32,  gn * hs[lane + 32]);
}

// gates[NN,256] = A[NN,192] @ Wc[192,256] + bc   (BM=64,BN=64,BK=16, 4x4 microtile)
__global__ void k_gemm() {
    __shared__ float As[64][16];
    __shared__ float Bs[16][64];
    int tid = threadIdx.x;
    int tx = tid & 15, ty = tid >> 4;
    int row0 = blockIdx.x * 64, col0 = blockIdx.y * 64;
    int lr = tid >> 2, lc = (tid & 3) * 4;
    int wr = tid >> 4, wc = (tid & 15) * 4;
    float acc[4][4];
#pragma unroll
    for (int i = 0; i < 4; i++)
#pragma unroll
        for (int j = 0; j < 4; j++) acc[i][j] = 0.f;

    int ar = row0 + lr;
    bool arok = ar < NN;
    const float* Aptr = g_A + (long)ar * KA + lc;

    for (int k0 = 0; k0 < KA; k0 += 16) {
        float4 av = arok ? *(const float4*)(Aptr + k0) : make_float4(0.f, 0.f, 0.f, 0.f);
        *(float4*)(&As[lr][lc]) = av;
        *(float4*)(&Bs[wr][wc]) = *(const float4*)(g_Wc + (long)(k0 + wr) * G4H + col0 + wc);
        __syncthreads();
#pragma unroll
        for (int kk = 0; kk < 16; kk++) {
            float4 b = *(float4*)(&Bs[kk][tx * 4]);
            float a0 = As[ty * 4 + 0][kk];
            float a1 = As[ty * 4 + 1][kk];
            float a2 = As[ty * 4 + 2][kk];
            float a3 = As[ty * 4 + 3][kk];
            acc[0][0] += a0 * b.x; acc[0][1] += a0 * b.y; acc[0][2] += a0 * b.z; acc[0][3] += a0 * b.w;
            acc[1][0] += a1 * b.x; acc[1][1] += a1 * b.y; acc[1][2] += a1 * b.z; acc[1][3] += a1 * b.w;
            acc[2][0] += a2 * b.x; acc[2][1] += a2 * b.y; acc[2][2] += a2 * b.z; acc[2][3] += a2 * b.w;
            acc[3][0] += a3 * b.x; acc[3][1] += a3 * b.y; acc[3][2] += a3 * b.z; acc[3][3] += a3 * b.w;
        }
        __syncthreads();
    }
    float4 bcv = *(const float4*)(g_bc + col0 + tx * 4);
#pragma unroll
    for (int i = 0; i < 4; i++) {
        int r = row0 + ty * 4 + i;
        if (r < NN) {
            float4 o;
            o.x = acc[i][0] + bcv.x; o.y = acc[i][1] + bcv.y;
            o.z = acc[i][2] + bcv.z; o.w = acc[i][3] + bcv.w;
            *(float4*)(g_gates + (long)r * G4H + col0 + tx * 4) = o;
        }
    }
}

__global__ void k_update() {
    int i = blockIdx.x * blockDim.x + threadIdx.x;
    if (i >= NN * HH) return;
    int n = i >> 6, j = i & 63;
    const float* gr = g_gates + (long)n * G4H;
    float si = sigm(gr[j]);
    float sf_ = sigm(gr[64 + j]);
    float so = sigm(gr[128 + j]);
    float m = fmaxf(gr[192 + j], 0.f);
    float c = tanhf(si * m + sf_ * g_c[i]);
    g_c[i] = c;
    g_h[i] = so * tanhf(c);
}

// ---------------- DGPool ----------------
__global__ void k_vnorm(const float* __restrict__ pv) {
    __shared__ float red[64];
    int t = threadIdx.x;
    float v = pv[t];
    red[t] = v * v;
    __syncthreads();
    for (int s = 32; s > 0; s >>= 1) { if (t < s) red[t] += red[t + s]; __syncthreads(); }
    g_v[t] = v / (sqrtf(red[0]) + 1e-8f);
}

__global__ void k_scores() {
    __shared__ float ws[8];
    int lane = threadIdx.x & 31, w = threadIdx.x >> 5;
    int n = blockIdx.x * 8 + w;
    float p = 0.f;
    if (n < NN)
        p = g_h[n * 64 + lane] * g_v[lane] + g_h[n * 64 + 32 + lane] * g_v[32 + lane];
    for (int o = 16; o; o >>= 1) p += __shfl_down_sync(0xffffffffu, p, o);
    if (lane == 0) {
        if (n < NN) g_raw[n] = p;
        ws[w] = (n < NN) ? p : 0.f;
    }
    __syncthreads();
    if (threadIdx.x == 0) {
        float s = 0.f, q = 0.f;
        for (int i = 0; i < 8; i++) { s += ws[i]; q += ws[i] * ws[i]; }
        atomicAdd(&g_ssum, s);
        atomicAdd(&g_ssq, q);
    }
}

__global__ void k_sfin() {
    float mean = g_ssum * (1.f / NN);
    float var = g_ssq * (1.f / NN) - mean * mean;
    g_smean = mean;
    g_sinv = 1.f / (sqrtf(fmaxf(var, 0.f)) + 1e-8f);
}

__global__ void k_standardize(float* __restrict__ out) {
    int n = blockIdx.x * blockDim.x + threadIdx.x;
    float pl = 0.f;
    if (n < NN) {
        float s = (g_raw[n] - g_smean) * g_sinv;
        out[1 + n] = s;
        float sg = sigm(s);
        g_sig[n] = sg;
        unsigned u = __float_as_uint(s);
        u = (u & 0x80000000u) ? ~u : (u | 0x80000000u);
        g_key[n] = u;
        pl = sg * (1.f - sg);
    }
    for (int o = 16; o; o >>= 1) pl += __shfl_down_sync(0xffffffffu, pl, o);
    __shared__ float sred[8];
    if ((threadIdx.x & 31) == 0) sred[threadIdx.x >> 5] = pl;
    __syncthreads();
    if (threadIdx.x == 0) {
        float s = 0.f;
        for (int i = 0; i < 8; i++) s += sred[i];
        atomicAdd(&g_ploss, s);
    }
}

__global__ void k_hist(int shift) {
    __shared__ unsigned sh[256];
    sh[threadIdx.x] = 0u;
    __syncthreads();
    unsigned pref = g_prefix;
    int n = blockIdx.x * blockDim.x + threadIdx.x;
    if (n < NN) {
        unsigned k = g_key[n];
        bool cand = (shift == 24) || ((k >> (shift + 8)) == (pref >> (shift + 8)));
        if (cand) atomicAdd(&sh[(k >> shift) & 255u], 1u);
    }
    __syncthreads();
    if (sh[threadIdx.x]) atomicAdd(&g_hist[threadIdx.x], sh[threadIdx.x]);
}

__global__ void k_scan(int shift) {
    if (threadIdx.x == 0) {
        unsigned kk = g_kk, cum = 0u;
        for (int b = 255; b >= 0; b--) {
            unsigned c = g_hist[b];
            if (cum + c >= kk) {
                g_prefix |= ((unsigned)b) << shift;
                g_kk = kk - cum;
                break;
            }
            cum += c;
        }
    }
    __syncthreads();
    g_hist[threadIdx.x] = 0u;
}

__global__ void k_sumhigh() {
    __shared__ float acc[64];
    if (threadIdx.x < 64) acc[threadIdx.x] = 0.f;
    __syncthreads();
    int lane = threadIdx.x & 31, w = threadIdx.x >> 5;
    int n = blockIdx.x * 8 + w;
    if (n < NN) {
        int inc = 0;
        if (lane == 0) {
            unsigned key = g_key[n], tau = g_prefix;
            if (key > tau) inc = 1;
            else if (key == tau) {
                unsigned tk = atomicAdd(&g_ticket, 1u);
                inc = (tk < g_kk) ? 1 : 0;
            }
        }
        inc = __shfl_sync(0xffffffffu, inc, 0);
        if (inc) {
            float sg = g_sig[n];
            atomicAdd(&acc[lane],      g_h[n * 64 + lane] * sg);
            atomicAdd(&acc[lane + 32], g_h[n * 64 + lane + 32] * sg);
        }
    }
    __syncthreads();
    if (threadIdx.x < 64) atomicAdd(&g_high[threadIdx.x], acc[threadIdx.x]);
}

// ---------------- raw-fMRI LSTM ----------------
// G[t, r] = sum_n W_ih[r, n] * ts[t, n]   (K-split with atomic accumulate)
__global__ void k_Ggemm(const float* __restrict__ Wih, const float* __restrict__ ts) {
    __shared__ float sW[32][65];
    __shared__ float sT[32][51];
    int r0 = blockIdx.y * 64;
    int kbeg = blockIdx.x * 313;
    int kend = min(NN, kbeg + 313);
    int tid = threadIdx.x;
    int r = tid & 63, tq = tid >> 6;
    float acc[13];
#pragma unroll
    for (int j = 0; j < 13; j++) acc[j] = 0.f;

    for (int k0 = kbeg; k0 < kend; k0 += 32) {
#pragma unroll
        for (int i = 0; i < 8; i++) {
            int flat = i * 256 + tid;
            int kk = flat & 31, rr = flat >> 5;
            int kg = k0 + kk;
            sW[kk][rr] = (kg < kend) ? Wih[(long)(r0 + rr) * NN + kg] : 0.f;
        }
#pragma unroll
        for (int i = 0; i < 7; i++) {
            int flat = i * 256 + tid;
            if (flat < 1600) {
                int kk = flat & 31, t = flat >> 5;
                int kg = k0 + kk;
                sT[kk][t] = (kg < kend) ? ts[(long)t * NN + kg] : 0.f;
            }
        }
        __syncthreads();
#pragma unroll
        for (int kk = 0; kk < 32; kk++) {
            float wv = sW[kk][r];
#pragma unroll
            for (int j = 0; j < 13; j++) {
                int t = tq + 4 * j;
                if (t < TSN) acc[j] += wv * sT[kk][t];
            }
        }
        __syncthreads();
    }
#pragma unroll
    for (int j = 0; j < 13; j++) {
        int t = tq + 4 * j;
        if (t < TSN) atomicAdd(&g_G[t * G4H + r0 + r], acc[j]);
    }
}

__global__ void k_lstm(const float* __restrict__ Whh, const float* __restrict__ bih,
                       const float* __restrict__ bhh) {
    __shared__ float sh[64], scc[64], sg[256];
    int r = threadIdx.x;
    float wr[64];
#pragma unroll
    for (int m = 0; m < 64; m++) wr[m] = Whh[r * 64 + m];
    float bias = bih[r] + bhh[r];
    if (r < 64) { sh[r] = 0.f; scc[r] = 0.f; }
    __syncthreads();
    for (int t = 0; t < TSN; t++) {
        float a0 = 0.f, a1 = 0.f, a2 = 0.f, a3 = 0.f;
#pragma unroll
        for (int m = 0; m < 64; m += 4) {
            a0 += wr[m] * sh[m];
            a1 += wr[m + 1] * sh[m + 1];
            a2 += wr[m + 2] * sh[m + 2];
            a3 += wr[m + 3] * sh[m + 3];
        }
        sg[r] = g_G[t * G4H + r] + bias + ((a0 + a1) + (a2 + a3));
        __syncthreads();
        if (r < 64) {
            float gi = sg[r], gf = sg[64 + r], gg = sg[128 + r], go = sg[192 + r];
            float c = sigm(gf) * scc[r] + sigm(gi) * tanhf(gg);
            scc[r] = c;
            sh[r] = sigm(go) * tanhf(c);
        }
        __syncthreads();
    }
    if (r < 64) g_hl[r] = sh[r];
}

// ---------------- fusion head ----------------
__global__ void k_final(const float* __restrict__ lng, const float* __restrict__ lnb,
                        const float* __restrict__ W1, const float* __restrict__ b1,
                        const float* __restrict__ W2, const float* __restrict__ b2,
                        float* __restrict__ out) {
    __shared__ float red[128], sf[128], sz[64];
    int tid = threadIdx.x;
    float x = (tid < 64) ? g_high[tid] * (1.f / KSEL) : g_hl[tid - 64];
    red[tid] = x;
    __syncthreads();
    for (int s = 64; s > 0; s >>= 1) { if (tid < s) red[tid] += red[tid + s]; __syncthreads(); }
    float mean = red[0] * (1.f / 128.f);
    __syncthreads();
    float d = x - mean;
    red[tid] = d * d;
    __syncthreads();
    for (int s = 64; s > 0; s >>= 1) { if (tid < s) red[tid] += red[tid + s]; __syncthreads(); }
    float var = red[0] * (1.f / 128.f);
    float y = d * rsqrtf(var + 1e-5f) * lng[tid] + lnb[tid];
    __syncthreads();
    sf[tid] = y;
    __syncthreads();
    if (tid < 64) {
        float a = b1[tid];
        for (int j = 0; j < 128; j++) a += sf[j] * W1[j * 64 + tid];
        sz[tid] = fmaxf(a, 0.f);
    }
    __syncthreads();
    red[tid] = (tid < 64) ? sz[tid] * W2[tid] : 0.f;
    __syncthreads();
    for (int s = 64; s > 0; s >>= 1) { if (tid < s) red[tid] += red[tid + s]; __syncthreads(); }
    if (tid == 0) out[0] = red[0] + b2[0];
    if (tid == 1) out[NN + 1] = g_ploss * (1.f / NN);
}

// ---------------- launch ----------------
extern "C" void kernel_launch(void* const* d_in, const int* in_sizes, int n_in,
                              void* d_out, int out_size) {
    const float*      xs   = (const float*)d_in[0];
    const void*       ei   = d_in[1];
    const float*      ea   = (const float*)d_in[2];
    const float*      h0   = (const float*)d_in[3];
    const float*      c0   = (const float*)d_in[4];
    const float*      ts   = (const float*)d_in[5];
    const float*      Wrel = (const float*)d_in[6];
    const float*      brel = (const float*)d_in[7];
    const float*      Wroot= (const float*)d_in[8];
    const float*      Wg   = (const float*)d_in[9];
    const float*      bg   = (const float*)d_in[10];
    const float*      pool = (const float*)d_in[11];
    const float*      lng  = (const float*)d_in[12];
    const float*      lnb  = (const float*)d_in[13];
    const float*      Wih  = (const float*)d_in[14];
    const float*      Whh  = (const float*)d_in[15];
    const float*      bih  = (const float*)d_in[16];
    const float*      bhh  = (const float*)d_in[17];
    const float*      W1   = (const float*)d_in[18];
    const float*      b1   = (const float*)d_in[19];
    const float*      W2   = (const float*)d_in[20];
    const float*      b2   = (const float*)d_in[21];
    float* out = (float*)d_out;

    k_detect<<<1, 32>>>(ei);
    k_decode<<<(EE + 255) / 256, 256>>>(ei);
    k_zero_misc<<<(NN + 255) / 256, 256>>>();
    k_deg<<<(EE + 255) / 256, 256>>>();
    k_init_nodes<<<(NN * HH + 255) / 256, 256>>>(h0, c0);
    k_gcn<<<(EE + 255) / 256, 256>>>();
    k_wc<<<(KA * G4H + 255) / 256, 256>>>(Wrel, brel, Wroot, Wg, bg);

    for (int t = 0; t < TT; t++) {
        const float* xt = xs + (long)t * NN * FF;
        k_zstats<<<1, 64>>>();
        k_colstats<<<160, 256>>>(xt);
        k_statsfin<<<1, 64>>>();
        k_prep<<<(NN * FF + 255) / 256, 256>>>(xt);
        k_scatter<<<EE / 8, 256>>>(ea + (long)t * EE);
        k_gemm<<<dim3((NN + 63) / 64, 4), 256>>>();
        k_update<<<(NN * HH + 255) / 256, 256>>>();
    }

    k_vnorm<<<1, 64>>>(pool);
    k_scores<<<(NN + 7) / 8, 256>>>();
    k_sfin<<<1, 1>>>();
    k_standardize<<<(NN + 255) / 256, 256>>>(out);
    for (int p = 0; p < 4; p++) {
        int shift = 24 - 8 * p;
        k_hist<<<(NN + 255) / 256, 256>>>(shift);
        k_scan<<<1, 256>>>(shift);
    }
    k_sumhigh<<<(NN + 7) / 8, 256>>>();

    k_Ggemm<<<dim3(64, 4), 256>>>(Wih, ts);
    k_lstm<<<1, 256>>>(Whh, bih, bhh);
    k_final<<<1, 128>>>(lng, lnb, W1, b1, W2, b2, out);
}